// round 10
// baseline (speedup 1.0000x reference)
#include <cuda_runtime.h>
#include <cuda_bf16.h>
#include <cuda_fp16.h>
#include <cstdint>
#include <cstddef>

// ---------------- problem constants ----------------
#define NB_B   64
#define MAXT   511
#define TP1    512
#define S_DIM  1024
#define H_DIM  4096

// ---------------- tiling ----------------
#define BM 128
#define BN 256            // H columns per chunk
#define BK 64             // K per pipeline stage
#define N_CHUNKS  (H_DIM / BN)     // 16
#define K_STAGES  (S_DIM / BK)     // 16
#define TOT_GS    (N_CHUNKS * K_STAGES)  // 256
#define MAX_TILES 256     // worst case ceil(64*510/128) = 255
#define NTHREADS  256     // 8 warps: 2(M) x 4(N), warp tile 64x64

#define ROW_B  144        // 64 bf16 = 128B data + 16B pad (conflict-free ldmatrix)

// ---------------- SMEM layout: 3 pipeline stages + scratch ----------------
#define A_BYTES   (BM * ROW_B)          // 18432
#define B_BYTES   (BN * ROW_B)          // 36864
#define STG_BYTES (A_BYTES + B_BYTES)   // 55296
#define SM_LG     (3 * STG_BYTES)       // 165888
#define SMEM_BYTES (SM_LG + 4096)       // 169984

// ---------------- scratch (device globals; BSS zero-initialized) ----------
__device__ __align__(1024) __nv_bfloat16 g_s[(size_t)NB_B * TP1 * S_DIM];   // COMPACTED live rows; tail stays 0
__device__ __align__(1024) __nv_bfloat16 g_w1t[(size_t)H_DIM * S_DIM];      // W1^T bf16 (N-major rows, K contig)
__device__ int g_act[(size_t)NB_B * MAXT];   // per compacted row: action id
__device__ int g_off[NB_B + 1];              // row offsets per batch
__device__ int g_nrows;                      // total live rows

// ---------------- PTX helpers ----------------
__device__ __forceinline__ uint32_t smem_u32(const void* p) {
    uint32_t a;
    asm("{ .reg .u64 t; cvta.to.shared.u64 t, %1; cvt.u32.u64 %0, t; }" : "=r"(a) : "l"(p));
    return a;
}

__device__ __forceinline__ void cp_async16(uint32_t dst, const void* src) {
    asm volatile("cp.async.cg.shared.global [%0], [%1], 16;" :: "r"(dst), "l"(src) : "memory");
}
#define CP_COMMIT()  asm volatile("cp.async.commit_group;" ::: "memory")
#define CP_WAIT1()   asm volatile("cp.async.wait_group 1;" ::: "memory")
#define CP_WAIT2()   asm volatile("cp.async.wait_group 2;" ::: "memory")

__device__ __forceinline__ void ldsm4(uint32_t* r, uint32_t addr) {
    asm volatile("ldmatrix.sync.aligned.m8n8.x4.shared.b16 {%0,%1,%2,%3}, [%4];"
                 : "=r"(r[0]), "=r"(r[1]), "=r"(r[2]), "=r"(r[3]) : "r"(addr));
}

// NOTE: bf16 A/B with f16 accumulators is not a valid mma combination, so the
// whole chain switches to fp16 operands (inputs s, W1 converted to fp16).
// Input quantization error fp16 (2^-11) is smaller than bf16 (2^-8).
__device__ __forceinline__ void mma16816_f16(uint32_t* d, const uint32_t* a, const uint32_t* b) {
    asm volatile(
        "mma.sync.aligned.m16n8k16.row.col.f16.f16.f16.f16 "
        "{%0,%1}, {%2,%3,%4,%5}, {%6,%7}, {%0,%1};"
        : "+r"(d[0]), "+r"(d[1])
        : "r"(a[0]), "r"(a[1]), "r"(a[2]), "r"(a[3]), "r"(b[0]), "r"(b[1]));
}

// ---------------- kernel 0: prefix sum of lengths (+ un-poison out) ----------
__global__ void prefix_kernel(const int* __restrict__ lengths, float* __restrict__ out) {
    if (threadIdx.x == 0) {
        out[0] = 0.0f;
        int acc = 0;
        for (int b = 0; b < NB_B; b++) {
            g_off[b] = acc;
            int l = lengths[b];
            if (l > MAXT) l = MAXT;
            if (l < 0) l = 0;
            acc += l;
        }
        g_off[NB_B] = acc;
        g_nrows = acc;
    }
}

// ---------------- kernel 1: compacting fp32->fp16 conversion of live rows ----
__global__ void conv_s_kernel(const float* __restrict__ s,
                              const int* __restrict__ lengths,
                              const int* __restrict__ actions) {
    int t = blockIdx.x;               // 0..MAXT-1
    int b = blockIdx.y;
    int len = lengths[b];
    if (len > MAXT) len = MAXT;
    if (t >= len) return;

    int dstRow = g_off[b] + t;
    const float4* src = (const float4*)(s + ((size_t)b * TP1 + t) * S_DIM);
    __half2* dst = (__half2*)(g_s + (size_t)dstRow * S_DIM);
    for (int i = threadIdx.x; i < S_DIM / 4; i += blockDim.x) {
        float4 v = src[i];
        dst[i * 2 + 0] = __floats2half2_rn(v.x, v.y);
        dst[i * 2 + 1] = __floats2half2_rn(v.z, v.w);
    }
    if (threadIdx.x == 0)
        g_act[dstRow] = actions[(size_t)b * MAXT + t];
}

// ---------------- kernel 2: W1 (S,H) fp32 -> W1^T (H,S) fp16 ----------------
__global__ void conv_w1t_kernel(const float* __restrict__ W1) {
    __shared__ float tile[32][33];
    int n0 = blockIdx.x * 32;
    int k0 = blockIdx.y * 32;
    for (int r = threadIdx.y; r < 32; r += 8)
        tile[r][threadIdx.x] = W1[(size_t)(k0 + r) * H_DIM + n0 + threadIdx.x];
    __syncthreads();
    for (int r = threadIdx.y; r < 32; r += 8)
        ((__half*)g_w1t)[(size_t)(n0 + r) * S_DIM + k0 + threadIdx.x] =
            __float2half(tile[threadIdx.x][r]);
}

// ---------------- main fused kernel (256 threads, 8 warps: 2M x 4N) ---------
__global__ void __launch_bounds__(NTHREADS, 1)
traj_main_kernel(const float* __restrict__ b1,
                 const float* __restrict__ W2,
                 const float* __restrict__ b2,
                 float* __restrict__ out) {
    int nrows = g_nrows;
    int m0 = blockIdx.x * BM;
    if (m0 >= nrows) return;          // tile beyond live rows

    extern __shared__ char smem[];
    uint32_t sb = smem_u32(smem);
    float* lg = (float*)(smem + SM_LG);

    int tid = threadIdx.x;
    int wid = tid >> 5;
    int lane = tid & 31;
    int wm = wid & 1;                 // M half (64 rows)
    int wn = wid >> 1;                // N quarter (64 cols)

    const __nv_bfloat16* Abase = g_s + (size_t)m0 * S_DIM;

    // per-lane ldmatrix base byte offsets (within a stage buffer)
    uint32_t aOff0 = (uint32_t)((wm * 64 + (lane & 15)) * ROW_B + ((lane >> 4) * 8) * 2);
    uint32_t bOff0 = (uint32_t)((wn * 64 + ((lane & 16) ? 8 : 0) + (lane & 7)) * ROW_B
                                + (((lane >> 3) & 1) * 8) * 2);

    auto issue = [&](int gs) {
        int nc = gs >> 4, s = gs & 15;
        int k0 = s * BK;
        const __nv_bfloat16* ag = Abase + k0;
        const __nv_bfloat16* bg = g_w1t + (size_t)(nc * BN) * S_DIM + k0;
        uint32_t stg = sb + (uint32_t)((gs % 3) * STG_BYTES);
        uint32_t Ab = stg;
        uint32_t Bb = stg + A_BYTES;
#pragma unroll
        for (int t = 0; t < 4; t++) {              // A: 128 rows x 8 chunks = 1024
            int idx = tid + t * NTHREADS;
            int row = idx >> 3, ch = idx & 7;
            cp_async16(Ab + row * ROW_B + ch * 16, ag + (size_t)row * S_DIM + ch * 8);
        }
#pragma unroll
        for (int t = 0; t < 8; t++) {              // B: 256 rows x 8 chunks = 2048
            int idx = tid + t * NTHREADS;
            int row = idx >> 3, ch = idx & 7;
            cp_async16(Bb + row * ROW_B + ch * 16, bg + (size_t)row * S_DIM + ch * 8);
        }
        CP_COMMIT();
    };

    uint32_t c[4][8][2];              // 64x64 warp tile, fp16 accum: [mt][nt][rowhalf] = half2(col j0,j1)
#pragma unroll
    for (int mt = 0; mt < 4; mt++)
#pragma unroll
        for (int nt = 0; nt < 8; nt++) {
            c[mt][nt][0] = 0u; c[mt][nt][1] = 0u;
        }

    uint32_t fa[2][16], fb[2][16];    // double-buffered fragments (one k16 step each)

    // load fragments for k-step kk of the stage at 'stg' into buffer 'buf'
    auto ldfr = [&](int buf, uint32_t stg, int kk) {
        uint32_t Ab = stg + aOff0 + (uint32_t)kk * 32;
        uint32_t Bb = stg + A_BYTES + bOff0 + (uint32_t)kk * 32;
        ldsm4(&fa[buf][0],  Ab);
        ldsm4(&fa[buf][4],  Ab + 16 * ROW_B);
        ldsm4(&fa[buf][8],  Ab + 32 * ROW_B);
        ldsm4(&fa[buf][12], Ab + 48 * ROW_B);
        ldsm4(&fb[buf][0],  Bb);
        ldsm4(&fb[buf][4],  Bb + 16 * ROW_B);
        ldsm4(&fb[buf][8],  Bb + 32 * ROW_B);
        ldsm4(&fb[buf][12], Bb + 48 * ROW_B);
    };
    // 32 MMAs on buffer 'buf'
    auto mmast = [&](int buf) {
#pragma unroll
        for (int mt = 0; mt < 4; mt++)
#pragma unroll
            for (int p = 0; p < 4; p++) {
                mma16816_f16(c[mt][2 * p],     &fa[buf][mt * 4], &fb[buf][p * 4]);
                mma16816_f16(c[mt][2 * p + 1], &fa[buf][mt * 4], &fb[buf][p * 4 + 2]);
            }
    };

    // per-chunk epilogue: promote fp16->fp32, relu + b1, 4-wide W2 dot,
    // quad-reduce, smem atomicAdd
    auto epilog = [&](int chunk) {
        float macc[4][2][4];
#pragma unroll
        for (int mt = 0; mt < 4; mt++)
#pragma unroll
            for (int h = 0; h < 2; h++)
#pragma unroll
                for (int k = 0; k < 4; k++) macc[mt][h][k] = 0.f;
        int nbase = chunk * BN + wn * 64;
#pragma unroll
        for (int mt = 0; mt < 4; mt++)
#pragma unroll
            for (int nt = 0; nt < 8; nt++) {
                int n0 = nbase + nt * 8 + (lane & 3) * 2;
                float2 f0 = __half22float2(*(__half2*)&c[mt][nt][0]);   // row q,   cols n0,n0+1
                float2 f1 = __half22float2(*(__half2*)&c[mt][nt][1]);   // row q+8, cols n0,n0+1
#pragma unroll
                for (int j = 0; j < 2; j++) {
                    int n = n0 + j;
                    float bb = __ldg(b1 + n);
                    float4 w = __ldg((const float4*)(W2 + (size_t)n * 32));
                    float h0 = fmaxf((j ? f0.y : f0.x) + bb, 0.f);
                    float h1 = fmaxf((j ? f1.y : f1.x) + bb, 0.f);
                    macc[mt][0][0] += h0 * w.x; macc[mt][0][1] += h0 * w.y;
                    macc[mt][0][2] += h0 * w.z; macc[mt][0][3] += h0 * w.w;
                    macc[mt][1][0] += h1 * w.x; macc[mt][1][1] += h1 * w.y;
                    macc[mt][1][2] += h1 * w.z; macc[mt][1][3] += h1 * w.w;
                }
                c[mt][nt][0] = 0u; c[mt][nt][1] = 0u;   // reset for next chunk
            }
#pragma unroll
        for (int mt = 0; mt < 4; mt++)
#pragma unroll
            for (int h = 0; h < 2; h++)
#pragma unroll
                for (int k = 0; k < 4; k++) {
                    float v = macc[mt][h][k];
                    v += __shfl_xor_sync(0xffffffffu, v, 1);
                    v += __shfl_xor_sync(0xffffffffu, v, 2);
                    macc[mt][h][k] = v;
                }
        if ((lane & 3) == 0) {
            int q = lane >> 2;
#pragma unroll
            for (int mt = 0; mt < 4; mt++)
#pragma unroll
                for (int h = 0; h < 2; h++) {
                    int r = wm * 64 + mt * 16 + h * 8 + q;
#pragma unroll
                    for (int k = 0; k < 4; k++)
                        atomicAdd(&lg[r * 4 + k], macc[mt][h][k]);
                }
        }
    };

    // ---- prologue ----
    lg[tid] = 0.f; lg[tid + 256] = 0.f;    // zero 512-entry logit table
    issue(0); issue(1); issue(2);
    CP_WAIT2();                            // stage 0 resident (this thread)
    __syncthreads();                       // all threads' stage-0 writes visible; lg zeroed
    ldfr(0, sb, 0);                        // stage 0, kk 0 -> buffer 0

#pragma unroll 1
    for (int gs = 0; gs < TOT_GS; gs++) {
        uint32_t stg = sb + (uint32_t)((gs % 3) * STG_BYTES);
        // invariant: buffer 0 holds kk0 frags of stage gs
        ldfr(1, stg, 1); mmast(0);
        ldfr(0, stg, 2); mmast(1);
        ldfr(1, stg, 3); mmast(0);
        if (gs + 1 < TOT_GS) {
            CP_WAIT1();                    // stage gs+1 group complete (this thread)
            __syncthreads();               // hides behind queued MMAs
            uint32_t nstg = sb + (uint32_t)(((gs + 1) % 3) * STG_BYTES);
            ldfr(0, nstg, 0);              // next stage kk0 while kk1-3 MMAs drain
            if (gs + 3 < TOT_GS) issue(gs + 3);   // refill freed buffer (gs%3)
        }
        mmast(1);                          // kk3
        if ((gs & 15) == 15) epilog(gs >> 4);
    }
    __syncthreads();                       // all epilogue atomics done

    // ---- per-row log-softmax + gather (mask implicit: rows compacted) ----
    float contrib = 0.f;
    if (tid < 128) {
        int r = m0 + tid;
        if (r < nrows) {
            float l0 = lg[tid * 4 + 0] + __ldg(b2 + 0);
            float l1 = lg[tid * 4 + 1] + __ldg(b2 + 1);
            float l2 = lg[tid * 4 + 2] + __ldg(b2 + 2);
            float l3 = lg[tid * 4 + 3] + __ldg(b2 + 3);
            float mx = fmaxf(fmaxf(l0, l1), fmaxf(l2, l3));
            float e = expf(l0 - mx) + expf(l1 - mx) + expf(l2 - mx) + expf(l3 - mx);
            float lse = mx + logf(e);
            int a = g_act[r];
            float la = (a == 0) ? l0 : (a == 1) ? l1 : (a == 2) ? l2 : l3;
            contrib = la - lse;
        }
    }
#pragma unroll
    for (int o = 16; o; o >>= 1) contrib += __shfl_xor_sync(0xffffffffu, contrib, o);
    __syncthreads();
    if (lane == 0) lg[512 + wid] = contrib;
    __syncthreads();
    if (tid == 0) {
        float tot = 0.f;
#pragma unroll
        for (int w = 0; w < 8; w++) tot += lg[512 + w];
        atomicAdd(out, -tot);
    }
}

// ---------------- launcher ----------------
extern "C" void kernel_launch(void* const* d_in, const int* in_sizes, int n_in,
                              void* d_out, int out_size) {
    const float* s_i     = (const float*)d_in[0];
    const int*   actions = (const int*)d_in[1];
    const int*   lengths = (const int*)d_in[2];
    const float* W1      = (const float*)d_in[3];
    const float* b1      = (const float*)d_in[4];
    const float* W2      = (const float*)d_in[5];
    const float* b2      = (const float*)d_in[6];
    float* out = (float*)d_out;

    static bool attr_set = false;
    if (!attr_set) {
        cudaFuncSetAttribute(traj_main_kernel,
                             cudaFuncAttributeMaxDynamicSharedMemorySize, SMEM_BYTES);
        attr_set = true;
    }

    prefix_kernel<<<1, 32>>>(lengths, out);
    conv_s_kernel<<<dim3(MAXT, NB_B), 128>>>(s_i, lengths, actions);
    conv_w1t_kernel<<<dim3(H_DIM / 32, S_DIM / 32), dim3(32, 8)>>>(W1);
    traj_main_kernel<<<MAX_TILES, NTHREADS, SMEM_BYTES>>>(b1, W2, b2, out);
}